// round 9
// baseline (speedup 1.0000x reference)
#include <cuda_runtime.h>
#include <math.h>

#define B_N   8
#define T_LEN 48000
#define MAX_H 60
#define C_N   100
#define NFORM 5

// ReduceWindowRewriter(base=16) level sizes for n=48000:
//  L0: 48000 -> 3000 tiles of 16 ; L1: 3000 (pad 3008) -> 188 ;
//  L2: 188 (pad 192) -> 12 ; L3: 12 naive sequential.
#define L1_N   3000
#define L1_PAD 3008
#define L2_N   188
#define L2_PAD 192
#define L3_N   12

__device__ float g_inner0[B_N][T_LEN];       // per-16-tile inclusive scans
__device__ float g_T1[B_N * L1_N];           // tile sums
__device__ float g_S1[B_N * L1_N];           // composed level-1 scan

// 2*pi split: C1 = fl32(2*pi), C2 = 2*pi - C1 (negative)
#define TWOPI_F   6.28318548202514648f
#define C2_ABS    1.7484556e-7f      /* -(2pi - fl32(2pi)) */
#define INV2PI_F  0.15915494309189535f

// ---------------- packed f32x2 helpers (per-lane IEEE RN) -------------------
typedef unsigned long long u64;
__device__ __forceinline__ u64 pk2(float lo, float hi) {
    u64 r; asm("mov.b64 %0, {%1, %2};" : "=l"(r) : "f"(lo), "f"(hi)); return r;
}
__device__ __forceinline__ void unpk2(u64 v, float& lo, float& hi) {
    asm("mov.b64 {%0, %1}, %2;" : "=f"(lo), "=f"(hi) : "l"(v));
}
__device__ __forceinline__ u64 add2(u64 a, u64 b) {
    u64 r; asm("add.rn.f32x2 %0, %1, %2;" : "=l"(r) : "l"(a), "l"(b)); return r;
}
__device__ __forceinline__ u64 mul2(u64 a, u64 b) {
    u64 r; asm("mul.rn.f32x2 %0, %1, %2;" : "=l"(r) : "l"(a), "l"(b)); return r;
}
__device__ __forceinline__ u64 fma2(u64 a, u64 b, u64 c) {
    u64 r; asm("fma.rn.f32x2 %0, %1, %2, %3;" : "=l"(r) : "l"(a), "l"(b), "l"(c)); return r;
}

// ---------------------------------------------------------------------------
// Kernel A: level-0 tiles. One thread per 16-tile (24000 tiles total).
// x[t] = fl( fl(fl32(2pi)*f0) * fl32(1/24000) ); sequential fold per tile.
// ---------------------------------------------------------------------------
__global__ void __launch_bounds__(128)
scan_tiles_kernel(const float* __restrict__ f0)
{
    int gid = blockIdx.x * blockDim.x + threadIdx.x;
    if (gid >= B_N * L1_N) return;
    int b = gid / L1_N;
    int j = gid - b * L1_N;
    const float INV_SR = 1.0f / 24000.0f;

    const float4* src = reinterpret_cast<const float4*>(f0 + b * T_LEN + j * 16);
    float4* dst = reinterpret_cast<float4*>(&g_inner0[b][j * 16]);

    float4 v0 = src[0], v1 = src[1], v2 = src[2], v3 = src[3];
    float in[16] = {v0.x, v0.y, v0.z, v0.w, v1.x, v1.y, v1.z, v1.w,
                    v2.x, v2.y, v2.z, v2.w, v3.x, v3.y, v3.z, v3.w};
    float o[16];
    float acc = 0.0f;
    #pragma unroll
    for (int k = 0; k < 16; k++) {
        float x = __fmul_rn(__fmul_rn(TWOPI_F, in[k]), INV_SR);
        acc = __fadd_rn(acc, x);
        o[k] = acc;
    }
    dst[0] = make_float4(o[0],  o[1],  o[2],  o[3]);
    dst[1] = make_float4(o[4],  o[5],  o[6],  o[7]);
    dst[2] = make_float4(o[8],  o[9],  o[10], o[11]);
    dst[3] = make_float4(o[12], o[13], o[14], o[15]);
    g_T1[gid] = acc;
}

// ---------------------------------------------------------------------------
// Kernel B: per-batch upper levels (L1..L3) + compose S1 -> global; also the
// final_phase output. One CTA per batch, 256 threads.
// ---------------------------------------------------------------------------
__global__ void __launch_bounds__(256)
scan_upper_kernel(const float* __restrict__ initial_phase,
                  float* __restrict__ out /* final_phase at tail */)
{
    int b   = blockIdx.x;
    int tid = threadIdx.x;
    __shared__ float sT1[L1_PAD];
    __shared__ float sT2[L2_PAD];
    __shared__ float sT3[L3_N];
    __shared__ float sS2[L2_N];

    for (int j = tid; j < L1_N; j += 256) sT1[j] = g_T1[b * L1_N + j];
    for (int j = L1_N + tid; j < L1_PAD; j += 256) sT1[j] = 0.0f;
    __syncthreads();

    // L1: 188 tiles of 16, sequential fold, in-place inner1.
    if (tid < L2_N) {
        float acc = 0.0f;
        int base = tid * 16;
        #pragma unroll
        for (int k = 0; k < 16; k++) {
            acc = __fadd_rn(acc, sT1[base + k]);
            sT1[base + k] = acc;
        }
        sT2[tid] = acc;
    }
    if (tid >= L2_N && tid < L2_PAD) sT2[tid] = 0.0f;
    __syncthreads();

    // L2: 12 tiles of 16.
    if (tid < L3_N) {
        float acc = 0.0f;
        int base = tid * 16;
        #pragma unroll
        for (int k = 0; k < 16; k++) {
            acc = __fadd_rn(acc, sT2[base + k]);
            sT2[base + k] = acc;
        }
        sT3[tid] = acc;
    }
    __syncthreads();

    // L3: naive sequential scan of 12.
    if (tid == 0) {
        float acc = 0.0f;
        #pragma unroll
        for (int i = 0; i < L3_N; i++) {
            acc = __fadd_rn(acc, sT3[i]);
            sT3[i] = acc;
        }
    }
    __syncthreads();

    // S2 = inner2 + exclusive(S3)
    if (tid < L2_N) {
        int j3 = tid >> 4;
        sS2[tid] = j3 ? __fadd_rn(sT2[tid], sT3[j3 - 1]) : sT2[tid];
    }
    __syncthreads();

    // S1 = inner1 + exclusive(S2) -> global
    for (int j = tid; j < L1_N; j += 256) {
        int j2 = j >> 4;
        g_S1[b * L1_N + j] = j2 ? __fadd_rn(sT1[j], sS2[j2 - 1]) : sT1[j];
    }

    // final_phase = fl(fl(fl(inner0[T-1] + S1[2998]) + ip)) % 2pi
    if (tid == 0) {
        float s1v = __fadd_rn(sT1[2998], sS2[186]);       // S1[2998]
        float s0  = __fadd_rn(g_inner0[b][T_LEN - 1], s1v);
        float ph  = __fadd_rn(s0, initial_phase[b]);
        out[B_N * T_LEN + b] = fmodf(ph, TWOPI_F);
    }
}

// ---------------------------------------------------------------------------
// Kernel C: oscillator. One thread per (b, t). Phase composed on the fly
// (bit-exact rw16). Whole harmonic-pair pipeline in packed f32x2 RN math;
// only rint / MUFU sin / MUFU rcp are scalar (per-lane identical rounding).
// ---------------------------------------------------------------------------
__global__ void __launch_bounds__(256)
osc_kernel(const float* __restrict__ f0,
           const float* __restrict__ amplitudes,
           const float* __restrict__ formant_freqs,
           const float* __restrict__ formant_bws,
           const float* __restrict__ formant_amps,
           const float* __restrict__ initial_phase,
           float* __restrict__ out)
{
    int idx = blockIdx.x * blockDim.x + threadIdx.x;
    if (idx >= B_N * T_LEN) return;
    int b = idx / T_LEN;
    int t = idx - b * T_LEN;

    float f0v = f0[idx];

    // Compose phase: fl( fl(inner0[t] + S1[t/16 - 1]) + ip )
    int jt = t >> 4;
    float s0 = g_inner0[b][t];
    if (jt) s0 = __fadd_rn(s0, g_S1[b * L1_N + jt - 1]);
    float phase = __fadd_rn(s0, initial_phase[b]);

    // Linear interp of formant params (align_corners=True), exact f32 replica.
    const float SRC_SCALE = (float)(99.0 / 47999.0);
    float src = __fmul_rn((float)t, SRC_SCALE);
    int i0 = (int)floorf(src);
    i0 = max(0, min(C_N - 2, i0));
    float frac = __fsub_rn(src, (float)i0);
    float w0   = __fsub_rn(1.0f, frac);

    const float* fq = formant_freqs + (b * C_N + i0) * NFORM;
    const float* fb = formant_bws   + (b * C_N + i0) * NFORM;
    const float* fa = formant_amps  + (b * C_N + i0) * NFORM;

    // Packed per-formant params (negated freq so packed sub == add).
    u64 nfreq2[NFORM], bw22[NFORM], num2[NFORM];
    #pragma unroll
    for (int f = 0; f < NFORM; f++) {
        float fr = __fadd_rn(__fmul_rn(fq[f], w0), __fmul_rn(fq[f + NFORM], frac));
        float bw = __fadd_rn(__fmul_rn(fb[f], w0), __fmul_rn(fb[f + NFORM], frac));
        float am = __fadd_rn(__fmul_rn(fa[f], w0), __fmul_rn(fa[f + NFORM], frac));
        float bw2 = __fmul_rn(bw, bw);
        float num = __fmul_rn(__fmul_rn(am, bw), bw);            // ref order
        float nfs = -__fmul_rn(fr,  0.00390625f);                // -(freq*2^-8)
        float b2s = __fmul_rn(bw2, 1.52587890625e-05f);          // *2^-16 exact
        float nms = __fmul_rn(num, 1.52587890625e-05f);
        nfreq2[f] = pk2(nfs, nfs);
        bw22[f]   = pk2(b2s, b2s);
        num2[f]   = pk2(nms, nms);
    }
    const u64 ONE2   = pk2(1.0f, 1.0f);
    const u64 P256_2 = pk2(0.00390625f, 0.00390625f);
    const u64 I2PI2  = pk2(INV2PI_F, INV2PI_F);
    const u64 NC1_2  = pk2(-TWOPI_F, -TWOPI_F);
    const u64 C2_2   = pk2(C2_ABS, C2_ABS);
    const u64 F0_2   = pk2(f0v, f0v);
    const u64 PH_2   = pk2(phase, phase);

    const float* arow = amplitudes + (size_t)idx * MAX_H;
    u64 acc2 = pk2(0.0f, 0.0f);

    for (int hc = 0; hc < MAX_H; hc += 4) {
        if (!(__fmul_rn(f0v, (float)(hc + 1)) < 12000.0f)) break;
        float4 a4 = *reinterpret_cast<const float4*>(arow + hc);
        float am4[4] = {a4.x, a4.y, a4.z, a4.w};

        #pragma unroll
        for (int p = 0; p < 2; p++) {
            float hf0 = (float)(hc + 2 * p + 1);
            float hf1 = (float)(hc + 2 * p + 2);
            u64 hf2 = pk2(hf0, hf1);

            u64 hq2 = mul2(F0_2, hf2);           // exact ref h_freq pair
            float hq0, hq1;
            unpk2(hq2, hq0, hq1);
            if (!(hq0 < 12000.0f)) { p = 2; break; }   // monotone cut
            // lane1 masked via amplitude (all lane intermediates finite)
            float amLo = am4[2 * p];
            float amHi = (hq1 < 12000.0f) ? am4[2 * p + 1] : 0.0f;

            // formant chain, packed
            u64 hfs2 = mul2(hq2, P256_2);        // *2^-8 exact per lane
            u64 Np2 = ONE2, Dp2 = ONE2;
            #pragma unroll
            for (int f = 0; f < NFORM; f++) {
                u64 d2   = add2(hfs2, nfreq2[f]);
                u64 den2 = fma2(d2, d2, bw22[f]);
                u64 nd2  = add2(den2, num2[f]);
                Np2 = mul2(Np2, nd2);
                Dp2 = mul2(Dp2, den2);
            }

            // sin reduction, packed (rint scalar on ALU pipe)
            u64 arg2 = mul2(PH_2, hf2);          // EXACT f32 product per lane
            u64 kp2  = mul2(arg2, I2PI2);
            float kp0, kp1;
            unpk2(kp2, kp0, kp1);
            u64 kq2 = pk2(rintf(kp0), rintf(kp1));
            u64 r2  = fma2(kq2, NC1_2, arg2);
            r2      = fma2(kq2, C2_2, r2);
            float r0, r1;
            unpk2(r2, r0, r1);
            u64 sv2 = pk2(__sinf(r0), __sinf(r1));

            // factor = Np/Dp via scalar MUFU rcp + packed mul
            float Dp0, Dp1;
            unpk2(Dp2, Dp0, Dp1);
            u64 rcp2 = pk2(__frcp_rn(Dp0) * 0.0f + __fdividef(1.0f, Dp0),
                           __fdividef(1.0f, Dp1));
            u64 fact2 = mul2(Np2, rcp2);

            // acc += am * sv * fact  (packed even/odd accumulators)
            u64 am2 = pk2(amLo, amHi);
            acc2 = fma2(mul2(am2, sv2), fact2, acc2);
        }
    }

    float accLo, accHi;
    unpk2(acc2, accLo, accHi);
    float acc = __fadd_rn(accLo, accHi);

    float voiced = (f0v > 0.0f) ? 1.0f : 0.0f;
    out[idx] = __fmul_rn(acc, voiced);
}

// ---------------------------------------------------------------------------
// Inputs (metadata order): f0 [B,T,1], amplitudes [B,T,60],
// formant_freqs [B,100,5], formant_bws [B,100,5], formant_amps [B,100,5],
// initial_phase [B,1,1].
// Output: signal [B,T] (384000 floats) then final_phase [B,1,1] (8 floats).
// ---------------------------------------------------------------------------
extern "C" void kernel_launch(void* const* d_in, const int* in_sizes, int n_in,
                              void* d_out, int out_size)
{
    const float* f0   = (const float*)d_in[0];
    const float* amps = (const float*)d_in[1];
    const float* ffq  = (const float*)d_in[2];
    const float* fbw  = (const float*)d_in[3];
    const float* fam  = (const float*)d_in[4];
    const float* ip   = (const float*)d_in[5];
    float* out = (float*)d_out;

    int tiles = B_N * L1_N;
    scan_tiles_kernel<<<(tiles + 127) / 128, 128>>>(f0);
    scan_upper_kernel<<<B_N, 256>>>(ip, out);

    int total = B_N * T_LEN;
    osc_kernel<<<(total + 255) / 256, 256>>>(f0, amps, ffq, fbw, fam, ip, out);
}

// round 10
// speedup vs baseline: 1.1052x; 1.1052x over previous
#include <cuda_runtime.h>
#include <math.h>

#define B_N   8
#define T_LEN 48000
#define MAX_H 60
#define C_N   100
#define NFORM 5

// ReduceWindowRewriter(base=16) level sizes for n=48000:
//  L0: 48000 -> 3000 tiles of 16 ; L1: 3000 (pad 3008) -> 188 ;
//  L2: 188 (pad 192) -> 12 ; L3: 12 naive sequential.
#define L1_N   3000
#define L1_PAD 3008
#define L2_N   188
#define L2_PAD 192
#define L3_N   12

__device__ float g_inner0[B_N][T_LEN];       // per-16-tile inclusive scans
__device__ float g_T1[B_N * L1_N];           // tile sums
__device__ float g_S1[B_N * L1_N];           // composed level-1 scan

// 2*pi split: C1 = fl32(2*pi), C2 = 2*pi - C1 (negative)
#define TWOPI_F   6.28318548202514648f
#define C2_ABS    1.7484556e-7f      /* -(2pi - fl32(2pi)) */
#define INV2PI_F  0.15915494309189535f

// ---------------- packed f32x2 helpers (per-lane IEEE RN) -------------------
typedef unsigned long long u64;
__device__ __forceinline__ u64 pk2(float lo, float hi) {
    u64 r; asm("mov.b64 %0, {%1, %2};" : "=l"(r) : "f"(lo), "f"(hi)); return r;
}
__device__ __forceinline__ void unpk2(u64 v, float& lo, float& hi) {
    asm("mov.b64 {%0, %1}, %2;" : "=f"(lo), "=f"(hi) : "l"(v));
}
__device__ __forceinline__ u64 add2(u64 a, u64 b) {
    u64 r; asm("add.rn.f32x2 %0, %1, %2;" : "=l"(r) : "l"(a), "l"(b)); return r;
}
__device__ __forceinline__ u64 mul2(u64 a, u64 b) {
    u64 r; asm("mul.rn.f32x2 %0, %1, %2;" : "=l"(r) : "l"(a), "l"(b)); return r;
}
__device__ __forceinline__ u64 fma2(u64 a, u64 b, u64 c) {
    u64 r; asm("fma.rn.f32x2 %0, %1, %2, %3;" : "=l"(r) : "l"(a), "l"(b), "l"(c)); return r;
}

// ---------------------------------------------------------------------------
// Kernel A: level-0 tiles. One thread per 16-tile (24000 tiles total).
// x[t] = fl( fl(fl32(2pi)*f0) * fl32(1/24000) ); sequential fold per tile.
// ---------------------------------------------------------------------------
__global__ void __launch_bounds__(128)
scan_tiles_kernel(const float* __restrict__ f0)
{
    int gid = blockIdx.x * blockDim.x + threadIdx.x;
    if (gid >= B_N * L1_N) return;
    int b = gid / L1_N;
    int j = gid - b * L1_N;
    const float INV_SR = 1.0f / 24000.0f;

    const float4* src = reinterpret_cast<const float4*>(f0 + b * T_LEN + j * 16);
    float4* dst = reinterpret_cast<float4*>(&g_inner0[b][j * 16]);

    float4 v0 = src[0], v1 = src[1], v2 = src[2], v3 = src[3];
    float in[16] = {v0.x, v0.y, v0.z, v0.w, v1.x, v1.y, v1.z, v1.w,
                    v2.x, v2.y, v2.z, v2.w, v3.x, v3.y, v3.z, v3.w};
    float o[16];
    float acc = 0.0f;
    #pragma unroll
    for (int k = 0; k < 16; k++) {
        float x = __fmul_rn(__fmul_rn(TWOPI_F, in[k]), INV_SR);
        acc = __fadd_rn(acc, x);
        o[k] = acc;
    }
    dst[0] = make_float4(o[0],  o[1],  o[2],  o[3]);
    dst[1] = make_float4(o[4],  o[5],  o[6],  o[7]);
    dst[2] = make_float4(o[8],  o[9],  o[10], o[11]);
    dst[3] = make_float4(o[12], o[13], o[14], o[15]);
    g_T1[gid] = acc;
}

// ---------------------------------------------------------------------------
// Kernel B: per-batch upper levels (L1..L3) + compose S1 -> global; also the
// final_phase output. One CTA per batch, 256 threads.
// ---------------------------------------------------------------------------
__global__ void __launch_bounds__(256)
scan_upper_kernel(const float* __restrict__ initial_phase,
                  float* __restrict__ out /* final_phase at tail */)
{
    int b   = blockIdx.x;
    int tid = threadIdx.x;
    __shared__ float sT1[L1_PAD];
    __shared__ float sT2[L2_PAD];
    __shared__ float sT3[L3_N];
    __shared__ float sS2[L2_N];

    for (int j = tid; j < L1_N; j += 256) sT1[j] = g_T1[b * L1_N + j];
    for (int j = L1_N + tid; j < L1_PAD; j += 256) sT1[j] = 0.0f;
    __syncthreads();

    // L1: 188 tiles of 16, sequential fold, in-place inner1.
    if (tid < L2_N) {
        float acc = 0.0f;
        int base = tid * 16;
        #pragma unroll
        for (int k = 0; k < 16; k++) {
            acc = __fadd_rn(acc, sT1[base + k]);
            sT1[base + k] = acc;
        }
        sT2[tid] = acc;
    }
    if (tid >= L2_N && tid < L2_PAD) sT2[tid] = 0.0f;
    __syncthreads();

    // L2: 12 tiles of 16.
    if (tid < L3_N) {
        float acc = 0.0f;
        int base = tid * 16;
        #pragma unroll
        for (int k = 0; k < 16; k++) {
            acc = __fadd_rn(acc, sT2[base + k]);
            sT2[base + k] = acc;
        }
        sT3[tid] = acc;
    }
    __syncthreads();

    // L3: naive sequential scan of 12.
    if (tid == 0) {
        float acc = 0.0f;
        #pragma unroll
        for (int i = 0; i < L3_N; i++) {
            acc = __fadd_rn(acc, sT3[i]);
            sT3[i] = acc;
        }
    }
    __syncthreads();

    // S2 = inner2 + exclusive(S3)
    if (tid < L2_N) {
        int j3 = tid >> 4;
        sS2[tid] = j3 ? __fadd_rn(sT2[tid], sT3[j3 - 1]) : sT2[tid];
    }
    __syncthreads();

    // S1 = inner1 + exclusive(S2) -> global
    for (int j = tid; j < L1_N; j += 256) {
        int j2 = j >> 4;
        g_S1[b * L1_N + j] = j2 ? __fadd_rn(sT1[j], sS2[j2 - 1]) : sT1[j];
    }

    // final_phase = fl(fl(fl(inner0[T-1] + S1[2998]) + ip)) % 2pi
    if (tid == 0) {
        float s1v = __fadd_rn(sT1[2998], sS2[186]);       // S1[2998]
        float s0  = __fadd_rn(g_inner0[b][T_LEN - 1], s1v);
        float ph  = __fadd_rn(s0, initial_phase[b]);
        out[B_N * T_LEN + b] = fmodf(ph, TWOPI_F);
    }
}

// ---------------------------------------------------------------------------
// Kernel C: oscillator. One thread per (b, t). Phase composed on the fly
// (bit-exact rw16). Harmonic pairs in packed f32x2 RN math; scalar only for
// rint (ALU) and MUFU sin/rcp. ONE division per pair:
//   inv = 1/(Dp0*Dp1); fact_i = Np_i * Dp_other * inv.
// ---------------------------------------------------------------------------
__global__ void __launch_bounds__(256)
osc_kernel(const float* __restrict__ f0,
           const float* __restrict__ amplitudes,
           const float* __restrict__ formant_freqs,
           const float* __restrict__ formant_bws,
           const float* __restrict__ formant_amps,
           const float* __restrict__ initial_phase,
           float* __restrict__ out)
{
    int idx = blockIdx.x * blockDim.x + threadIdx.x;
    if (idx >= B_N * T_LEN) return;
    int b = idx / T_LEN;
    int t = idx - b * T_LEN;

    float f0v = f0[idx];

    // Compose phase: fl( fl(inner0[t] + S1[t/16 - 1]) + ip )
    int jt = t >> 4;
    float s0 = g_inner0[b][t];
    if (jt) s0 = __fadd_rn(s0, g_S1[b * L1_N + jt - 1]);
    float phase = __fadd_rn(s0, initial_phase[b]);

    // Linear interp of formant params (align_corners=True), exact f32 replica.
    const float SRC_SCALE = (float)(99.0 / 47999.0);
    float src = __fmul_rn((float)t, SRC_SCALE);
    int i0 = (int)floorf(src);
    i0 = max(0, min(C_N - 2, i0));
    float frac = __fsub_rn(src, (float)i0);
    float w0   = __fsub_rn(1.0f, frac);

    const float* fq = formant_freqs + (b * C_N + i0) * NFORM;
    const float* fb = formant_bws   + (b * C_N + i0) * NFORM;
    const float* fa = formant_amps  + (b * C_N + i0) * NFORM;

    // Packed per-formant params (negated freq so packed sub == add).
    u64 nfreq2[NFORM], bw22[NFORM], num2[NFORM];
    #pragma unroll
    for (int f = 0; f < NFORM; f++) {
        float fr = __fadd_rn(__fmul_rn(fq[f], w0), __fmul_rn(fq[f + NFORM], frac));
        float bw = __fadd_rn(__fmul_rn(fb[f], w0), __fmul_rn(fb[f + NFORM], frac));
        float am = __fadd_rn(__fmul_rn(fa[f], w0), __fmul_rn(fa[f + NFORM], frac));
        float bw2 = __fmul_rn(bw, bw);
        float num = __fmul_rn(__fmul_rn(am, bw), bw);            // ref order
        float nfs = -__fmul_rn(fr,  0.00390625f);                // -(freq*2^-8)
        float b2s = __fmul_rn(bw2, 1.52587890625e-05f);          // *2^-16 exact
        float nms = __fmul_rn(num, 1.52587890625e-05f);
        nfreq2[f] = pk2(nfs, nfs);
        bw22[f]   = pk2(b2s, b2s);
        num2[f]   = pk2(nms, nms);
    }
    const u64 ONE2   = pk2(1.0f, 1.0f);
    const u64 P256_2 = pk2(0.00390625f, 0.00390625f);
    const u64 I2PI2  = pk2(INV2PI_F, INV2PI_F);
    const u64 NC1_2  = pk2(-TWOPI_F, -TWOPI_F);
    const u64 C2_2   = pk2(C2_ABS, C2_ABS);
    const u64 F0_2   = pk2(f0v, f0v);
    const u64 PH_2   = pk2(phase, phase);

    const float* arow = amplitudes + (size_t)idx * MAX_H;
    u64 acc2 = pk2(0.0f, 0.0f);

    for (int hc = 0; hc < MAX_H; hc += 4) {
        if (!(__fmul_rn(f0v, (float)(hc + 1)) < 12000.0f)) break;
        float4 a4 = *reinterpret_cast<const float4*>(arow + hc);
        float am4[4] = {a4.x, a4.y, a4.z, a4.w};

        #pragma unroll
        for (int p = 0; p < 2; p++) {
            float hf0 = (float)(hc + 2 * p + 1);
            float hf1 = (float)(hc + 2 * p + 2);
            u64 hf2 = pk2(hf0, hf1);

            u64 hq2 = mul2(F0_2, hf2);           // exact ref h_freq pair
            float hq0, hq1;
            unpk2(hq2, hq0, hq1);
            if (!(hq0 < 12000.0f)) { p = 2; break; }   // monotone cut
            // lane1 masked via amplitude (all lane intermediates finite)
            float amLo = am4[2 * p];
            float amHi = (hq1 < 12000.0f) ? am4[2 * p + 1] : 0.0f;

            // formant chain, packed
            u64 hfs2 = mul2(hq2, P256_2);        // *2^-8 exact per lane
            u64 Np2 = ONE2, Dp2 = ONE2;
            #pragma unroll
            for (int f = 0; f < NFORM; f++) {
                u64 d2   = add2(hfs2, nfreq2[f]);
                u64 den2 = fma2(d2, d2, bw22[f]);
                u64 nd2  = add2(den2, num2[f]);
                Np2 = mul2(Np2, nd2);
                Dp2 = mul2(Dp2, den2);
            }

            // sin reduction, packed (rint scalar on ALU pipe)
            u64 arg2 = mul2(PH_2, hf2);          // EXACT f32 product per lane
            u64 kp2  = mul2(arg2, I2PI2);
            float kp0, kp1;
            unpk2(kp2, kp0, kp1);
            u64 kq2 = pk2(rintf(kp0), rintf(kp1));
            u64 r2  = fma2(kq2, NC1_2, arg2);
            r2      = fma2(kq2, C2_2, r2);
            float r0, r1;
            unpk2(r2, r0, r1);
            u64 sv2 = pk2(__sinf(r0), __sinf(r1));

            // ONE division per pair: inv = 1/(Dp0*Dp1);
            // fact0 = Np0*Dp1*inv, fact1 = Np1*Dp0*inv
            float Dp0, Dp1;
            unpk2(Dp2, Dp0, Dp1);
            float inv = __fdividef(1.0f, __fmul_rn(Dp0, Dp1));
            u64 cross2 = pk2(Dp1, Dp0);
            u64 inv2   = pk2(inv, inv);
            u64 fact2  = mul2(mul2(Np2, cross2), inv2);

            // acc += am * sv * fact  (packed even/odd accumulators)
            u64 am2 = pk2(amLo, amHi);
            acc2 = fma2(mul2(am2, sv2), fact2, acc2);
        }
    }

    float accLo, accHi;
    unpk2(acc2, accLo, accHi);
    float acc = __fadd_rn(accLo, accHi);

    float voiced = (f0v > 0.0f) ? 1.0f : 0.0f;
    out[idx] = __fmul_rn(acc, voiced);
}

// ---------------------------------------------------------------------------
// Inputs (metadata order): f0 [B,T,1], amplitudes [B,T,60],
// formant_freqs [B,100,5], formant_bws [B,100,5], formant_amps [B,100,5],
// initial_phase [B,1,1].
// Output: signal [B,T] (384000 floats) then final_phase [B,1,1] (8 floats).
// ---------------------------------------------------------------------------
extern "C" void kernel_launch(void* const* d_in, const int* in_sizes, int n_in,
                              void* d_out, int out_size)
{
    const float* f0   = (const float*)d_in[0];
    const float* amps = (const float*)d_in[1];
    const float* ffq  = (const float*)d_in[2];
    const float* fbw  = (const float*)d_in[3];
    const float* fam  = (const float*)d_in[4];
    const float* ip   = (const float*)d_in[5];
    float* out = (float*)d_out;

    int tiles = B_N * L1_N;
    scan_tiles_kernel<<<(tiles + 127) / 128, 128>>>(f0);
    scan_upper_kernel<<<B_N, 256>>>(ip, out);

    int total = B_N * T_LEN;
    osc_kernel<<<(total + 255) / 256, 256>>>(f0, amps, ffq, fbw, fam, ip, out);
}

// round 11
// speedup vs baseline: 1.1101x; 1.0044x over previous
#include <cuda_runtime.h>
#include <math.h>

#define B_N   8
#define T_LEN 48000
#define MAX_H 60
#define C_N   100
#define NFORM 5

// ReduceWindowRewriter(base=16) level sizes for n=48000:
//  L0: 48000 -> 3000 tiles of 16 ; L1: 3000 (pad 3008) -> 188 ;
//  L2: 188 (pad 192) -> 12 ; L3: 12 naive sequential.
#define L1_N   3000
#define L1_PAD 3008
#define L2_N   188
#define L2_PAD 192
#define L3_N   12

__device__ float g_inner0[B_N][T_LEN];       // per-16-tile inclusive scans
__device__ float g_T1[B_N * L1_N];           // tile sums
__device__ float g_S1[B_N * L1_N];           // composed level-1 scan

// 2*pi split: C1 = fl32(2*pi), C2 = 2*pi - C1 (negative)
#define TWOPI_F   6.28318548202514648f
#define C2_ABS    1.7484556e-7f      /* -(2pi - fl32(2pi)) */
#define INV2PI_F  0.15915494309189535f
#define RMAGIC    12582912.0f        /* 1.5 * 2^23 : RN-ties-even rounder */

// ---------------- packed f32x2 helpers (per-lane IEEE RN) -------------------
typedef unsigned long long u64;
__device__ __forceinline__ u64 pk2(float lo, float hi) {
    u64 r; asm("mov.b64 %0, {%1, %2};" : "=l"(r) : "f"(lo), "f"(hi)); return r;
}
__device__ __forceinline__ void unpk2(u64 v, float& lo, float& hi) {
    asm("mov.b64 {%0, %1}, %2;" : "=f"(lo), "=f"(hi) : "l"(v));
}
__device__ __forceinline__ u64 add2(u64 a, u64 b) {
    u64 r; asm("add.rn.f32x2 %0, %1, %2;" : "=l"(r) : "l"(a), "l"(b)); return r;
}
__device__ __forceinline__ u64 mul2(u64 a, u64 b) {
    u64 r; asm("mul.rn.f32x2 %0, %1, %2;" : "=l"(r) : "l"(a), "l"(b)); return r;
}
__device__ __forceinline__ u64 fma2(u64 a, u64 b, u64 c) {
    u64 r; asm("fma.rn.f32x2 %0, %1, %2, %3;" : "=l"(r) : "l"(a), "l"(b), "l"(c)); return r;
}

// ---------------------------------------------------------------------------
// Kernel A: level-0 tiles. One thread per 16-tile (24000 tiles total).
// x[t] = fl( fl(fl32(2pi)*f0) * fl32(1/24000) ); sequential fold per tile.
// ---------------------------------------------------------------------------
__global__ void __launch_bounds__(128)
scan_tiles_kernel(const float* __restrict__ f0)
{
    int gid = blockIdx.x * blockDim.x + threadIdx.x;
    if (gid >= B_N * L1_N) return;
    int b = gid / L1_N;
    int j = gid - b * L1_N;
    const float INV_SR = 1.0f / 24000.0f;

    const float4* src = reinterpret_cast<const float4*>(f0 + b * T_LEN + j * 16);
    float4* dst = reinterpret_cast<float4*>(&g_inner0[b][j * 16]);

    float4 v0 = src[0], v1 = src[1], v2 = src[2], v3 = src[3];
    float in[16] = {v0.x, v0.y, v0.z, v0.w, v1.x, v1.y, v1.z, v1.w,
                    v2.x, v2.y, v2.z, v2.w, v3.x, v3.y, v3.z, v3.w};
    float o[16];
    float acc = 0.0f;
    #pragma unroll
    for (int k = 0; k < 16; k++) {
        float x = __fmul_rn(__fmul_rn(TWOPI_F, in[k]), INV_SR);
        acc = __fadd_rn(acc, x);
        o[k] = acc;
    }
    dst[0] = make_float4(o[0],  o[1],  o[2],  o[3]);
    dst[1] = make_float4(o[4],  o[5],  o[6],  o[7]);
    dst[2] = make_float4(o[8],  o[9],  o[10], o[11]);
    dst[3] = make_float4(o[12], o[13], o[14], o[15]);
    g_T1[gid] = acc;
}

// ---------------------------------------------------------------------------
// Kernel B: per-batch upper levels (L1..L3) + compose S1 -> global; also the
// final_phase output. One CTA per batch, 256 threads.
// ---------------------------------------------------------------------------
__global__ void __launch_bounds__(256)
scan_upper_kernel(const float* __restrict__ initial_phase,
                  float* __restrict__ out /* final_phase at tail */)
{
    int b   = blockIdx.x;
    int tid = threadIdx.x;
    __shared__ float sT1[L1_PAD];
    __shared__ float sT2[L2_PAD];
    __shared__ float sT3[L3_N];
    __shared__ float sS2[L2_N];

    for (int j = tid; j < L1_N; j += 256) sT1[j] = g_T1[b * L1_N + j];
    for (int j = L1_N + tid; j < L1_PAD; j += 256) sT1[j] = 0.0f;
    __syncthreads();

    // L1: 188 tiles of 16, sequential fold, in-place inner1.
    if (tid < L2_N) {
        float acc = 0.0f;
        int base = tid * 16;
        #pragma unroll
        for (int k = 0; k < 16; k++) {
            acc = __fadd_rn(acc, sT1[base + k]);
            sT1[base + k] = acc;
        }
        sT2[tid] = acc;
    }
    if (tid >= L2_N && tid < L2_PAD) sT2[tid] = 0.0f;
    __syncthreads();

    // L2: 12 tiles of 16.
    if (tid < L3_N) {
        float acc = 0.0f;
        int base = tid * 16;
        #pragma unroll
        for (int k = 0; k < 16; k++) {
            acc = __fadd_rn(acc, sT2[base + k]);
            sT2[base + k] = acc;
        }
        sT3[tid] = acc;
    }
    __syncthreads();

    // L3: naive sequential scan of 12.
    if (tid == 0) {
        float acc = 0.0f;
        #pragma unroll
        for (int i = 0; i < L3_N; i++) {
            acc = __fadd_rn(acc, sT3[i]);
            sT3[i] = acc;
        }
    }
    __syncthreads();

    // S2 = inner2 + exclusive(S3)
    if (tid < L2_N) {
        int j3 = tid >> 4;
        sS2[tid] = j3 ? __fadd_rn(sT2[tid], sT3[j3 - 1]) : sT2[tid];
    }
    __syncthreads();

    // S1 = inner1 + exclusive(S2) -> global
    for (int j = tid; j < L1_N; j += 256) {
        int j2 = j >> 4;
        g_S1[b * L1_N + j] = j2 ? __fadd_rn(sT1[j], sS2[j2 - 1]) : sT1[j];
    }

    // final_phase = fl(fl(fl(inner0[T-1] + S1[2998]) + ip)) % 2pi
    if (tid == 0) {
        float s1v = __fadd_rn(sT1[2998], sS2[186]);       // S1[2998]
        float s0  = __fadd_rn(g_inner0[b][T_LEN - 1], s1v);
        float ph  = __fadd_rn(s0, initial_phase[b]);
        out[B_N * T_LEN + b] = fmodf(ph, TWOPI_F);
    }
}

// ---------------------------------------------------------------------------
// Kernel C: oscillator. One thread per (b, t). Branch-free inner loop:
// harmonic count nh precomputed exactly; last (possibly half) pair peeled.
// Packed f32x2 RN math; scalar only MUFU sin / one MUFU rcp per pair.
// ---------------------------------------------------------------------------
struct PairCtx {
    u64 nfreq2[NFORM], bw22[NFORM], num2[NFORM];
    u64 F0S_2, PH_2, ONE2, I2PI2, NC1_2, C2_2, MAG2, NMAG2;
};

__device__ __forceinline__ u64 pair_term(const PairCtx& c, u64 hf2, u64 am2)
{
    // formant chain, packed
    u64 hfs2 = mul2(c.F0S_2, hf2);        // == 2^-8 * fl(f0*h) per lane (exact)
    u64 Np2 = c.ONE2, Dp2 = c.ONE2;
    #pragma unroll
    for (int f = 0; f < NFORM; f++) {
        u64 d2   = add2(hfs2, c.nfreq2[f]);
        u64 den2 = fma2(d2, d2, c.bw22[f]);
        u64 nd2  = add2(den2, c.num2[f]);
        Np2 = mul2(Np2, nd2);
        Dp2 = mul2(Dp2, den2);
    }

    // sin reduction, fully packed (magic-number rint == rintf for 0<=kp<2^22)
    u64 arg2 = mul2(c.PH_2, hf2);         // EXACT f32 product per lane
    u64 kp2  = mul2(arg2, c.I2PI2);
    u64 kq2  = add2(add2(kp2, c.MAG2), c.NMAG2);
    u64 r2   = fma2(kq2, c.NC1_2, arg2);
    r2       = fma2(kq2, c.C2_2, r2);
    float r0, r1;
    unpk2(r2, r0, r1);
    u64 sv2 = pk2(__sinf(r0), __sinf(r1));

    // one division per pair: inv = 1/(Dp0*Dp1); fact_i = Np_i * Dp_other * inv
    float Dp0, Dp1;
    unpk2(Dp2, Dp0, Dp1);
    float inv = __fdividef(1.0f, __fmul_rn(Dp0, Dp1));
    u64 cross2 = pk2(Dp1, Dp0);
    u64 inv2   = pk2(inv, inv);
    u64 fact2  = mul2(mul2(Np2, cross2), inv2);

    return mul2(mul2(am2, sv2), fact2);
}

__global__ void __launch_bounds__(256)
osc_kernel(const float* __restrict__ f0,
           const float* __restrict__ amplitudes,
           const float* __restrict__ formant_freqs,
           const float* __restrict__ formant_bws,
           const float* __restrict__ formant_amps,
           const float* __restrict__ initial_phase,
           float* __restrict__ out)
{
    int idx = blockIdx.x * blockDim.x + threadIdx.x;
    if (idx >= B_N * T_LEN) return;
    int b = idx / T_LEN;
    int t = idx - b * T_LEN;

    float f0v = f0[idx];

    // Compose phase: fl( fl(inner0[t] + S1[t/16 - 1]) + ip )
    int jt = t >> 4;
    float s0 = g_inner0[b][t];
    if (jt) s0 = __fadd_rn(s0, g_S1[b * L1_N + jt - 1]);
    float phase = __fadd_rn(s0, initial_phase[b]);

    // Exact harmonic count: nh = max{h in [0,60] : fl(f0*h) < 12000}
    int nh = min(MAX_H, (int)__fdividef(12000.0f, f0v));
    while (nh > 0 && !(__fmul_rn(f0v, (float)nh) < 12000.0f)) nh--;
    while (nh < MAX_H && __fmul_rn(f0v, (float)(nh + 1)) < 12000.0f) nh++;
    int npairs = (nh + 1) >> 1;            // >= 15 for f0 in [100,400]

    // Linear interp of formant params (align_corners=True), exact f32 replica.
    const float SRC_SCALE = (float)(99.0 / 47999.0);
    float src = __fmul_rn((float)t, SRC_SCALE);
    int i0 = (int)floorf(src);
    i0 = max(0, min(C_N - 2, i0));
    float frac = __fsub_rn(src, (float)i0);
    float w0   = __fsub_rn(1.0f, frac);

    const float* fq = formant_freqs + (b * C_N + i0) * NFORM;
    const float* fb = formant_bws   + (b * C_N + i0) * NFORM;
    const float* fa = formant_amps  + (b * C_N + i0) * NFORM;

    PairCtx c;
    #pragma unroll
    for (int f = 0; f < NFORM; f++) {
        float fr = __fadd_rn(__fmul_rn(fq[f], w0), __fmul_rn(fq[f + NFORM], frac));
        float bw = __fadd_rn(__fmul_rn(fb[f], w0), __fmul_rn(fb[f + NFORM], frac));
        float am = __fadd_rn(__fmul_rn(fa[f], w0), __fmul_rn(fa[f + NFORM], frac));
        float bw2 = __fmul_rn(bw, bw);
        float num = __fmul_rn(__fmul_rn(am, bw), bw);            // ref order
        float nfs = -__fmul_rn(fr,  0.00390625f);                // -(freq*2^-8)
        float b2s = __fmul_rn(bw2, 1.52587890625e-05f);          // *2^-16 exact
        float nms = __fmul_rn(num, 1.52587890625e-05f);
        c.nfreq2[f] = pk2(nfs, nfs);
        c.bw22[f]   = pk2(b2s, b2s);
        c.num2[f]   = pk2(nms, nms);
    }
    float f0s = __fmul_rn(f0v, 0.00390625f);   // exact 2^-8 scale of f0
    c.F0S_2 = pk2(f0s, f0s);
    c.PH_2  = pk2(phase, phase);
    c.ONE2  = pk2(1.0f, 1.0f);
    c.I2PI2 = pk2(INV2PI_F, INV2PI_F);
    c.NC1_2 = pk2(-TWOPI_F, -TWOPI_F);
    c.C2_2  = pk2(C2_ABS, C2_ABS);
    c.MAG2  = pk2(RMAGIC, RMAGIC);
    c.NMAG2 = pk2(-RMAGIC, -RMAGIC);

    const u64* arow2 =
        reinterpret_cast<const u64*>(amplitudes + (size_t)idx * MAX_H);

    u64 acc2 = pk2(0.0f, 0.0f);
    u64 hf2  = pk2(1.0f, 2.0f);
    const u64 TWO2 = pk2(2.0f, 2.0f);

    // Main pairs: uniform trip count, no compares/branches inside.
    #pragma unroll 2
    for (int pi = 0; pi < npairs - 1; pi++) {
        acc2 = add2(acc2, pair_term(c, hf2, arow2[pi]));
        hf2  = add2(hf2, TWO2);
    }

    // Peeled last pair: mask hi lane if nh is odd (h_hi = nh+1 excluded).
    {
        u64 am2 = arow2[npairs - 1];
        if (nh & 1) am2 &= 0x00000000FFFFFFFFull;
        acc2 = add2(acc2, pair_term(c, hf2, am2));
    }

    float accLo, accHi;
    unpk2(acc2, accLo, accHi);
    float acc = __fadd_rn(accLo, accHi);

    float voiced = (f0v > 0.0f) ? 1.0f : 0.0f;
    out[idx] = __fmul_rn(acc, voiced);
}

// ---------------------------------------------------------------------------
// Inputs (metadata order): f0 [B,T,1], amplitudes [B,T,60],
// formant_freqs [B,100,5], formant_bws [B,100,5], formant_amps [B,100,5],
// initial_phase [B,1,1].
// Output: signal [B,T] (384000 floats) then final_phase [B,1,1] (8 floats).
// ---------------------------------------------------------------------------
extern "C" void kernel_launch(void* const* d_in, const int* in_sizes, int n_in,
                              void* d_out, int out_size)
{
    const float* f0   = (const float*)d_in[0];
    const float* amps = (const float*)d_in[1];
    const float* ffq  = (const float*)d_in[2];
    const float* fbw  = (const float*)d_in[3];
    const float* fam  = (const float*)d_in[4];
    const float* ip   = (const float*)d_in[5];
    float* out = (float*)d_out;

    int tiles = B_N * L1_N;
    scan_tiles_kernel<<<(tiles + 127) / 128, 128>>>(f0);
    scan_upper_kernel<<<B_N, 256>>>(ip, out);

    int total = B_N * T_LEN;
    osc_kernel<<<(total + 255) / 256, 256>>>(f0, amps, ffq, fbw, fam, ip, out);
}